// round 10
// baseline (speedup 1.0000x reference)
#include <cuda_runtime.h>

#define NN 50000          // nodes
#define D_IN 64
#define HID 128
#define D_OUT 64

// ---------------- scratch (device globals: allocation-free rule) -------------
__device__ __align__(16) float g_agg1[NN * D_IN];   // 12.8 MB
__device__ __align__(16) float g_h1  [NN * HID];    // 25.6 MB
__device__ __align__(16) float g_agg2[NN * HID];    // 25.6 MB
__device__ __align__(16) float g_h2  [NN * HID];    // 25.6 MB
__device__ int   g_cnt[NN];
__device__ float g_inv[NN];
__device__ int   g_detect;   // OR of sampled odd 32-bit words of edge_index

// ---------------- helpers ----------------------------------------------------
__device__ __forceinline__ int edge_at(const void* ei, long long i, bool is64) {
    if (is64) return (int)__ldg(((const long long*)ei) + i);
    return __ldg(((const int*)ei) + i);
}

// ---------------- zero scratch ------------------------------------------------
__global__ void k_zero() {
    int idx = blockIdx.x * blockDim.x + threadIdx.x;
    int stride = gridDim.x * blockDim.x;
    for (int i = idx; i < NN * D_IN; i += stride) g_agg1[i] = 0.f;
    for (int i = idx; i < NN * HID;  i += stride) g_agg2[i] = 0.f;
    for (int i = idx; i < NN;        i += stride) g_cnt[i] = 0;
    if (idx == 0) g_detect = 0;
}

// ---------------- int32 vs int64 edge dtype detection ------------------------
// If buffer is int64 (values < 2^31, nonneg), every odd 32-bit word is 0.
// If int32, odd words are uniform node ids in [0,50000): P(2048 samples all 0) ~ 0.
__global__ void k_detect(const int* __restrict__ w, long long twoE) {
    int t = threadIdx.x;
    int v = 0;
    #pragma unroll
    for (int s = 0; s < 8; s++) {
        long long i = 2LL * (t + s * 256) + 1;
        if (i < twoE) v |= w[i];
    }
    if (v) atomicOr(&g_detect, 1);
}

// ---------------- in-degree histogram ----------------------------------------
__global__ void k_count(const void* __restrict__ ei, int E) {
    bool is64 = (g_detect == 0);
    int idx = blockIdx.x * blockDim.x + threadIdx.x;
    int stride = gridDim.x * blockDim.x;
    for (int e = idx; e < E; e += stride) {
        int dst = edge_at(ei, (long long)E + e, is64);
        atomicAdd(&g_cnt[dst], 1);
    }
}

__global__ void k_inv() {
    int n = blockIdx.x * blockDim.x + threadIdx.x;
    if (n < NN) {
        int c = g_cnt[n];
        g_inv[n] = 1.0f / (float)(c > 1 ? c : 1);
    }
}

// ---------------- mean-aggregate scatter (sum part; mean applied in GEMM) ----
// D floats per row; each edge handled by D/4 lanes, one float4 vector-atomic each.
template <int D>
__global__ void k_agg(const float* __restrict__ feat, const void* __restrict__ ei,
                      float* __restrict__ agg, int E) {
    constexpr int TPE = D / 4;              // threads per edge (16 or 32)
    bool is64 = (g_detect == 0);
    int gid = blockIdx.x * blockDim.x + threadIdx.x;
    int lane = gid % TPE;
    int group = gid / TPE;
    int ngroups = (gridDim.x * blockDim.x) / TPE;
    const float4* f4 = (const float4*)feat;
    for (int e = group; e < E; e += ngroups) {
        int src = edge_at(ei, e, is64);
        int dst = edge_at(ei, (long long)E + e, is64);
        float4 v = f4[(size_t)src * TPE + lane];
        atomicAdd(((float4*)(agg + (size_t)dst * D)) + lane, v);   // red.global.v4.f32
    }
}

// ---------------- fused dual-GEMM + bias + relu -------------------------------
// C[n, 0:OC] = act( scale(n)*A1[n,:K1] @ B1 + A2[n,:K2] @ B2 + bias ),
// where scale(n) = g_inv[n] if useInv (mean aggregation) else 1.
template <int K1, int K2, int OC, bool RELU>
__global__ __launch_bounds__(256) void k_fused(
    const float* __restrict__ A1, const float* __restrict__ A2,
    const float* __restrict__ B1, const float* __restrict__ B2,
    const float* __restrict__ bias, float* __restrict__ C, bool useInv)
{
    constexpr int BN = 64, BK = 32;
    constexpr int CG = OC / 4;        // column groups (32 or 16)
    constexpr int TY = 256 / CG;      // row groups   (8 or 16)
    constexpr int TM = BN / TY;       // rows/thread  (8 or 4)
    __shared__ float sA[BK][BN];      // k-major
    __shared__ float sB[BK][OC];

    const int n0 = blockIdx.x * BN;
    const int tid = threadIdx.x;
    const int tx = tid % CG;
    const int ty = tid / CG;

    float acc[TM][4] = {};

    auto do_part = [&](const float* A, const float* B, int K, bool scl) {
        for (int kt = 0; kt < K; kt += BK) {
            // load A tile: thread loads 8 consecutive k for one row
            {
                int n = tid >> 2;
                int kk = (tid & 3) * 8;
                int gn = n0 + n;
                float s = 1.0f;
                const float* row = nullptr;
                if (gn < NN) {
                    row = A + (size_t)gn * K + kt + kk;
                    if (scl) s = g_inv[gn];
                }
                #pragma unroll
                for (int j = 0; j < 8; j++) {
                    float v = row ? row[j] * s : 0.f;
                    sA[kk + j][n] = v;
                }
            }
            // load B tile (coalesced)
            {
                #pragma unroll
                for (int i = 0; i < (BK * OC) / 256; i++) {
                    int idx = tid + i * 256;
                    int kr = idx / OC, c = idx % OC;
                    sB[kr][c] = B[(size_t)(kt + kr) * OC + c];
                }
            }
            __syncthreads();
            #pragma unroll
            for (int k = 0; k < BK; k++) {
                float4 b = *(const float4*)&sB[k][tx * 4];
                float av[TM];
                #pragma unroll
                for (int m = 0; m < TM; m += 4) {
                    float4 t = *(const float4*)&sA[k][ty * TM + m];
                    av[m] = t.x; av[m + 1] = t.y; av[m + 2] = t.z; av[m + 3] = t.w;
                }
                #pragma unroll
                for (int m = 0; m < TM; m++) {
                    acc[m][0] += av[m] * b.x;
                    acc[m][1] += av[m] * b.y;
                    acc[m][2] += av[m] * b.z;
                    acc[m][3] += av[m] * b.w;
                }
            }
            __syncthreads();
        }
    };

    do_part(A1, B1, K1, useInv);
    if constexpr (K2 > 0) do_part(A2, B2, K2, false);

    #pragma unroll
    for (int m = 0; m < TM; m++) {
        int gn = n0 + ty * TM + m;
        if (gn < NN) {
            #pragma unroll
            for (int j = 0; j < 4; j++) {
                float v = acc[m][j] + bias[tx * 4 + j];
                if (RELU) v = fmaxf(v, 0.f);
                C[(size_t)gn * OC + tx * 4 + j] = v;
            }
        }
    }
}

// ---------------- launch ------------------------------------------------------
extern "C" void kernel_launch(void* const* d_in, const int* in_sizes, int n_in,
                              void* d_out, int out_size) {
    const float* x     = (const float*)d_in[0];
    const void*  ei    = d_in[1];
    const float* W_l1  = (const float*)d_in[2];
    const float* b_l1  = (const float*)d_in[3];
    const float* W_r1  = (const float*)d_in[4];
    const float* W_l2  = (const float*)d_in[5];
    const float* b_l2  = (const float*)d_in[6];
    const float* W_r2  = (const float*)d_in[7];
    const float* W_out = (const float*)d_in[8];
    const float* b_out = (const float*)d_in[9];
    float* out = (float*)d_out;

    long long twoE = (long long)in_sizes[1];
    int E = (int)(twoE / 2);

    float *agg1, *agg2, *h1, *h2;
    cudaGetSymbolAddress((void**)&agg1, g_agg1);
    cudaGetSymbolAddress((void**)&agg2, g_agg2);
    cudaGetSymbolAddress((void**)&h1,   g_h1);
    cudaGetSymbolAddress((void**)&h2,   g_h2);

    const int NB = (NN + 63) / 64;   // 782 GEMM blocks

    k_zero  <<<2048, 256>>>();
    k_detect<<<1,    256>>>((const int*)ei, twoE);
    k_count <<<1024, 256>>>(ei, E);
    k_inv   <<<(NN + 255) / 256, 256>>>();

    // layer 1: agg1 = sum x[src] -> dst ;  h1 = relu(mean*W_l1 + x*W_r1 + b_l1)
    k_agg<D_IN><<<4096, 256>>>(x, ei, agg1, E);
    k_fused<D_IN, D_IN, HID, true><<<NB, 256>>>(agg1, x, W_l1, W_r1, b_l1, h1, true);

    // layer 2: agg2 = sum h1[src] -> dst ; h2 = relu(mean*W_l2 + h1*W_r2 + b_l2)
    k_agg<HID><<<4096, 256>>>(h1, ei, agg2, E);
    k_fused<HID, HID, HID, true><<<NB, 256>>>(agg2, h1, W_l2, W_r2, b_l2, h2, true);

    // output projection (no relu, no mean scaling)
    k_fused<HID, 0, D_OUT, false><<<NB, 256>>>(h2, nullptr, W_out, nullptr, b_out, out, false);
}